// round 2
// baseline (speedup 1.0000x reference)
#include <cuda_runtime.h>
#include <math.h>

#define NB  16
#define LL  1024
#define HH  768
#define OUTW (4*HH)

// Scratch (allocation-free rule: __device__ globals)
__device__ float g_xp[(size_t)NB*LL*HH];   // relu(x1 @ W^T + b)   48 MB
__device__ float g_yp[(size_t)NB*LL*HH];   // relu(x2 @ W^T + b)   48 MB
__device__ float g_sc[(size_t)NB*LL*LL];   // scores / alpha       64 MB

// ============================================================================
// Tiled fp32 GEMMs: 128x128 tile, BK=8, 256 threads, 8x8 microtile,
// double-buffered shared memory, single __syncthreads per K-tile.
// ============================================================================

// ---- Projection: C = relu(A[M,K] @ W[N,K]^T + bias), A = x1 or x2 by z ----
__global__ __launch_bounds__(256, 2) void proj_kernel(
    const float* __restrict__ X1, const float* __restrict__ X2,
    const float* __restrict__ W,  const float* __restrict__ bias)
{
    const float* A = blockIdx.z ? X2 : X1;
    float*       C = blockIdx.z ? g_yp : g_xp;

    __shared__ float As[2][8][128];
    __shared__ float Bs[2][8][128];

    const int tid = threadIdx.x;
    const int m0  = blockIdx.y * 128;
    const int n0  = blockIdx.x * 128;

    // tile-load layout (both operands K-contiguous): 128 rows x 8 cols
    const int lr = tid >> 1;            // row in tile 0..127
    const int lc = (tid & 1) << 2;      // 0 or 4

    const float* Ap = A + (size_t)(m0 + lr) * HH + lc;
    const float* Bp = W + (size_t)(n0 + lr) * HH + lc;

    const int trow = (tid >> 4) << 3;   // 0..120
    const int tcol = (tid & 15) << 3;   // 0..120

    float acc[8][8];
    #pragma unroll
    for (int i = 0; i < 8; i++)
        #pragma unroll
        for (int j = 0; j < 8; j++) acc[i][j] = 0.f;

    float4 ar = *(const float4*)Ap;
    float4 br = *(const float4*)Bp;
    As[0][lc+0][lr]=ar.x; As[0][lc+1][lr]=ar.y; As[0][lc+2][lr]=ar.z; As[0][lc+3][lr]=ar.w;
    Bs[0][lc+0][lr]=br.x; Bs[0][lc+1][lr]=br.y; Bs[0][lc+2][lr]=br.z; Bs[0][lc+3][lr]=br.w;
    __syncthreads();

    const int nk = HH / 8;
    int buf = 0;
    for (int kt = 0; kt < nk; ++kt) {
        if (kt + 1 < nk) {
            ar = *(const float4*)(Ap + (kt+1)*8);
            br = *(const float4*)(Bp + (kt+1)*8);
        }
        #pragma unroll
        for (int k = 0; k < 8; ++k) {
            float4 a0 = *(const float4*)&As[buf][k][trow];
            float4 a1 = *(const float4*)&As[buf][k][trow+4];
            float4 b0 = *(const float4*)&Bs[buf][k][tcol];
            float4 b1 = *(const float4*)&Bs[buf][k][tcol+4];
            float ra[8] = {a0.x,a0.y,a0.z,a0.w,a1.x,a1.y,a1.z,a1.w};
            float rb[8] = {b0.x,b0.y,b0.z,b0.w,b1.x,b1.y,b1.z,b1.w};
            #pragma unroll
            for (int i = 0; i < 8; i++)
                #pragma unroll
                for (int j = 0; j < 8; j++)
                    acc[i][j] = fmaf(ra[i], rb[j], acc[i][j]);
        }
        if (kt + 1 < nk) {
            const int nb = buf ^ 1;
            As[nb][lc+0][lr]=ar.x; As[nb][lc+1][lr]=ar.y; As[nb][lc+2][lr]=ar.z; As[nb][lc+3][lr]=ar.w;
            Bs[nb][lc+0][lr]=br.x; Bs[nb][lc+1][lr]=br.y; Bs[nb][lc+2][lr]=br.z; Bs[nb][lc+3][lr]=br.w;
            __syncthreads();
            buf = nb;
        }
    }

    #pragma unroll
    for (int i = 0; i < 8; i++) {
        float* cp = C + (size_t)(m0 + trow + i) * HH + n0 + tcol;
        #pragma unroll
        for (int j = 0; j < 8; j += 4) {
            float4 v;
            v.x = fmaxf(acc[i][j+0] + bias[n0+tcol+j+0], 0.f);
            v.y = fmaxf(acc[i][j+1] + bias[n0+tcol+j+1], 0.f);
            v.z = fmaxf(acc[i][j+2] + bias[n0+tcol+j+2], 0.f);
            v.w = fmaxf(acc[i][j+3] + bias[n0+tcol+j+3], 0.f);
            *(float4*)(cp + j) = v;
        }
    }
}

// ---- Scores: S[b] = Xp[b] @ Yp[b]^T  (both K-contiguous, K=768) ----
__global__ __launch_bounds__(256, 2) void scores_kernel()
{
    const int b = blockIdx.z;
    const float* A  = g_xp + (size_t)b * LL * HH;
    const float* Bm = g_yp + (size_t)b * LL * HH;
    float*       C  = g_sc + (size_t)b * LL * LL;

    __shared__ float As[2][8][128];
    __shared__ float Bs[2][8][128];

    const int tid = threadIdx.x;
    const int m0  = blockIdx.y * 128;
    const int n0  = blockIdx.x * 128;

    const int lr = tid >> 1;
    const int lc = (tid & 1) << 2;

    const float* Ap = A  + (size_t)(m0 + lr) * HH + lc;
    const float* Bp = Bm + (size_t)(n0 + lr) * HH + lc;

    const int trow = (tid >> 4) << 3;
    const int tcol = (tid & 15) << 3;

    float acc[8][8];
    #pragma unroll
    for (int i = 0; i < 8; i++)
        #pragma unroll
        for (int j = 0; j < 8; j++) acc[i][j] = 0.f;

    float4 ar = *(const float4*)Ap;
    float4 br = *(const float4*)Bp;
    As[0][lc+0][lr]=ar.x; As[0][lc+1][lr]=ar.y; As[0][lc+2][lr]=ar.z; As[0][lc+3][lr]=ar.w;
    Bs[0][lc+0][lr]=br.x; Bs[0][lc+1][lr]=br.y; Bs[0][lc+2][lr]=br.z; Bs[0][lc+3][lr]=br.w;
    __syncthreads();

    const int nk = HH / 8;
    int buf = 0;
    for (int kt = 0; kt < nk; ++kt) {
        if (kt + 1 < nk) {
            ar = *(const float4*)(Ap + (kt+1)*8);
            br = *(const float4*)(Bp + (kt+1)*8);
        }
        #pragma unroll
        for (int k = 0; k < 8; ++k) {
            float4 a0 = *(const float4*)&As[buf][k][trow];
            float4 a1 = *(const float4*)&As[buf][k][trow+4];
            float4 b0 = *(const float4*)&Bs[buf][k][tcol];
            float4 b1 = *(const float4*)&Bs[buf][k][tcol+4];
            float ra[8] = {a0.x,a0.y,a0.z,a0.w,a1.x,a1.y,a1.z,a1.w};
            float rb[8] = {b0.x,b0.y,b0.z,b0.w,b1.x,b1.y,b1.z,b1.w};
            #pragma unroll
            for (int i = 0; i < 8; i++)
                #pragma unroll
                for (int j = 0; j < 8; j++)
                    acc[i][j] = fmaf(ra[i], rb[j], acc[i][j]);
        }
        if (kt + 1 < nk) {
            const int nb = buf ^ 1;
            As[nb][lc+0][lr]=ar.x; As[nb][lc+1][lr]=ar.y; As[nb][lc+2][lr]=ar.z; As[nb][lc+3][lr]=ar.w;
            Bs[nb][lc+0][lr]=br.x; Bs[nb][lc+1][lr]=br.y; Bs[nb][lc+2][lr]=br.z; Bs[nb][lc+3][lr]=br.w;
            __syncthreads();
            buf = nb;
        }
    }

    #pragma unroll
    for (int i = 0; i < 8; i++) {
        float* cp = C + (size_t)(m0 + trow + i) * LL + n0 + tcol;
        #pragma unroll
        for (int j = 0; j < 8; j += 4) {
            float4 v = {acc[i][j+0], acc[i][j+1], acc[i][j+2], acc[i][j+3]};
            *(float4*)(cp + j) = v;
        }
    }
}

// ---- Masked row softmax over L2, in place in g_sc. One block per (b,i). ----
// MASK IS INT32 (bool inputs are materialized as int32 by the harness).
__global__ __launch_bounds__(256) void softmax_kernel(const int* __restrict__ mask2)
{
    const int b = blockIdx.y, i = blockIdx.x, tid = threadIdx.x;
    float* row = g_sc + ((size_t)b * LL + i) * LL;
    const int* mrow = mask2 + (size_t)b * LL;

    float4 s = *(const float4*)(row + tid * 4);
    int4   m = *(const int4*)(mrow + tid * 4);
    float v[4];
    v[0] = m.x ? -INFINITY : s.x;
    v[1] = m.y ? -INFINITY : s.y;
    v[2] = m.z ? -INFINITY : s.z;
    v[3] = m.w ? -INFINITY : s.w;

    float mx = fmaxf(fmaxf(v[0], v[1]), fmaxf(v[2], v[3]));
    #pragma unroll
    for (int o = 16; o > 0; o >>= 1) mx = fmaxf(mx, __shfl_xor_sync(0xffffffffu, mx, o));

    __shared__ float red[8];
    if ((tid & 31) == 0) red[tid >> 5] = mx;
    __syncthreads();
    float bm = red[0];
    #pragma unroll
    for (int w = 1; w < 8; w++) bm = fmaxf(bm, red[w]);

    float e[4];
    float sum = 0.f;
    #pragma unroll
    for (int q = 0; q < 4; q++) { e[q] = expf(v[q] - bm); sum += e[q]; }  // exp(-inf)=0
    #pragma unroll
    for (int o = 16; o > 0; o >>= 1) sum += __shfl_xor_sync(0xffffffffu, sum, o);

    __syncthreads();   // all bm reads done before red is reused
    if ((tid & 31) == 0) red[tid >> 5] = sum;
    __syncthreads();
    float bs = 0.f;
    #pragma unroll
    for (int w = 0; w < 8; w++) bs += red[w];
    const float inv = 1.0f / bs;

    float4 o4 = {e[0]*inv, e[1]*inv, e[2]*inv, e[3]*inv};
    *(float4*)(row + tid * 4) = o4;
}

// ---- Att (NN) + fused concat_dot_diff epilogue ----
// att[b] = alpha[b] (1024x1024) @ x2[b] (1024x768)
// out[b,i,:] = [ x1 | att | x1*att | x1-att ]
__global__ __launch_bounds__(256, 2) void att_kernel(
    const float* __restrict__ X2, const float* __restrict__ X1, float* __restrict__ OUT)
{
    const int b = blockIdx.z;
    const float* A = g_sc + (size_t)b * LL * LL;   // [1024, 1024] K-contiguous
    const float* V = X2   + (size_t)b * LL * HH;   // [1024, 768]  N-contiguous

    __shared__ float As[2][8][128];
    __shared__ float Bs[2][8][128];

    const int tid = threadIdx.x;
    const int m0  = blockIdx.y * 128;
    const int n0  = blockIdx.x * 128;

    // A tile: 128 rows x 8 k, transposed into smem
    const int lr = tid >> 1;
    const int lc = (tid & 1) << 2;
    const float* Ap = A + (size_t)(m0 + lr) * LL + lc;

    // B tile: 8 k-rows x 128 n-cols, direct
    const int brr = tid >> 5;            // 0..7
    const int bcc = (tid & 31) << 2;     // 0..124
    const float* Bp = V + (size_t)brr * HH + n0 + bcc;

    const int trow = (tid >> 4) << 3;
    const int tcol = (tid & 15) << 3;

    float acc[8][8];
    #pragma unroll
    for (int i = 0; i < 8; i++)
        #pragma unroll
        for (int j = 0; j < 8; j++) acc[i][j] = 0.f;

    float4 ar  = *(const float4*)Ap;
    float4 brv = *(const float4*)Bp;
    As[0][lc+0][lr]=ar.x; As[0][lc+1][lr]=ar.y; As[0][lc+2][lr]=ar.z; As[0][lc+3][lr]=ar.w;
    *(float4*)&Bs[0][brr][bcc] = brv;
    __syncthreads();

    const int nk = LL / 8;   // 128
    int buf = 0;
    for (int kt = 0; kt < nk; ++kt) {
        if (kt + 1 < nk) {
            ar  = *(const float4*)(Ap + (kt+1)*8);
            brv = *(const float4*)(Bp + (size_t)(kt+1)*8*HH);
        }
        #pragma unroll
        for (int k = 0; k < 8; ++k) {
            float4 a0 = *(const float4*)&As[buf][k][trow];
            float4 a1 = *(const float4*)&As[buf][k][trow+4];
            float4 b0 = *(const float4*)&Bs[buf][k][tcol];
            float4 b1 = *(const float4*)&Bs[buf][k][tcol+4];
            float ra[8] = {a0.x,a0.y,a0.z,a0.w,a1.x,a1.y,a1.z,a1.w};
            float rb[8] = {b0.x,b0.y,b0.z,b0.w,b1.x,b1.y,b1.z,b1.w};
            #pragma unroll
            for (int i = 0; i < 8; i++)
                #pragma unroll
                for (int j = 0; j < 8; j++)
                    acc[i][j] = fmaf(ra[i], rb[j], acc[i][j]);
        }
        if (kt + 1 < nk) {
            const int nb = buf ^ 1;
            As[nb][lc+0][lr]=ar.x; As[nb][lc+1][lr]=ar.y; As[nb][lc+2][lr]=ar.z; As[nb][lc+3][lr]=ar.w;
            *(float4*)&Bs[nb][brr][bcc] = brv;
            __syncthreads();
            buf = nb;
        }
    }

    // fused concat epilogue
    #pragma unroll
    for (int i = 0; i < 8; i++) {
        const int row = m0 + trow + i;
        const float* xp = X1  + ((size_t)b * LL + row) * HH   + n0 + tcol;
        float*       op = OUT + ((size_t)b * LL + row) * OUTW + n0 + tcol;
        #pragma unroll
        for (int j = 0; j < 8; j += 4) {
            float4 a = {acc[i][j+0], acc[i][j+1], acc[i][j+2], acc[i][j+3]};
            float4 x = *(const float4*)(xp + j);
            *(float4*)(op + j)          = x;                                    // x1
            *(float4*)(op + HH + j)     = a;                                    // att
            float4 p = {x.x*a.x, x.y*a.y, x.z*a.z, x.w*a.w};
            *(float4*)(op + 2*HH + j)   = p;                                    // x1*att
            float4 d = {x.x-a.x, x.y-a.y, x.z-a.z, x.w-a.w};
            *(float4*)(op + 3*HH + j)   = d;                                    // x1-att
        }
    }
}

// ============================================================================
// Launch: inputs in metadata order x1, x2, x1_mask(unused), x2_mask, W, b
// ============================================================================
extern "C" void kernel_launch(void* const* d_in, const int* in_sizes, int n_in,
                              void* d_out, int out_size)
{
    (void)in_sizes; (void)n_in; (void)out_size;
    const float* x1   = (const float*)d_in[0];
    const float* x2   = (const float*)d_in[1];
    const int*   x2m  = (const int*)d_in[3];
    const float* W    = (const float*)d_in[4];
    const float* bias = (const float*)d_in[5];
    float*       out  = (float*)d_out;

    dim3 gProj(HH/128, (NB*LL)/128, 2);     // (6, 128, 2)
    proj_kernel<<<gProj, 256>>>(x1, x2, W, bias);

    dim3 gSc(LL/128, LL/128, NB);           // (8, 8, 16)
    scores_kernel<<<gSc, 256>>>();

    dim3 gSm(LL, NB);                       // (1024, 16)
    softmax_kernel<<<gSm, 256>>>(x2m);

    dim3 gAtt(HH/128, LL/128, NB);          // (6, 8, 16)
    att_kernel<<<gAtt, 256>>>(x2, x1, out);
}

// round 4
// speedup vs baseline: 2.0902x; 2.0902x over previous
#include <cuda_runtime.h>
#include <cuda_bf16.h>
#include <math.h>
#include <stdint.h>

#define NB 16
#define LL 1024
#define HH 768
#define OUTW (4*HH)
#define KCP (HH/32)   // 24 k-chunks for proj/scores
#define KCA (LL/32)   // 32 k-chunks for att

// ---------------------------------------------------------------------------
// Packed scratch: layout [row][chunk][128B = 32 bf16 hi | 32 bf16 lo]
// uint4 arrays guarantee 16B alignment for cp.async.
// ---------------------------------------------------------------------------
__device__ uint4 g_x1p[(size_t)NB*LL*KCP*8];   // 48 MB  (8 uint4 = 128B per chunk-row)
__device__ uint4 g_x2p[(size_t)NB*LL*KCP*8];   // 48 MB
__device__ uint4 g_wp [(size_t)HH*KCP*8];      // 2.25 MB
__device__ uint4 g_xpp[(size_t)NB*LL*KCP*8];   // 48 MB  relu(x1 W^T + b), packed
__device__ uint4 g_ypp[(size_t)NB*LL*KCP*8];   // 48 MB
__device__ uint4 g_ap [(size_t)NB*LL*KCA*8];   // 64 MB  alpha packed
__device__ uint4 g_vtp[(size_t)NB*HH*KCA*8];   // 48 MB  x2^T packed (rows=h, k=j)
__device__ float g_sc [(size_t)NB*LL*LL];      // 64 MB  scores fp32

// ---------------------------------------------------------------------------
// Helpers
// ---------------------------------------------------------------------------
__device__ __forceinline__ uint32_t smem_u32(const void* p) {
    uint32_t a;
    asm("{ .reg .u64 t; cvta.to.shared.u64 t, %1; cvt.u32.u64 %0, t; }"
        : "=r"(a) : "l"(p));
    return a;
}

// split 4 fp32 -> 2x bf16x2 hi + 2x bf16x2 lo (bit patterns)
__device__ __forceinline__ void split4(float4 v, uint32_t& h0, uint32_t& h1,
                                       uint32_t& l0, uint32_t& l1) {
    __nv_bfloat162 a = __floats2bfloat162_rn(v.x, v.y);
    __nv_bfloat162 b = __floats2bfloat162_rn(v.z, v.w);
    float2 fa = __bfloat1622float2(a), fb = __bfloat1622float2(b);
    __nv_bfloat162 c = __floats2bfloat162_rn(v.x - fa.x, v.y - fa.y);
    __nv_bfloat162 d = __floats2bfloat162_rn(v.z - fb.x, v.w - fb.y);
    h0 = *reinterpret_cast<uint32_t*>(&a);
    h1 = *reinterpret_cast<uint32_t*>(&b);
    l0 = *reinterpret_cast<uint32_t*>(&c);
    l1 = *reinterpret_cast<uint32_t*>(&d);
}

#define CP16(dst, src) \
    asm volatile("cp.async.cg.shared.global [%0], [%1], 16;" :: "r"(dst), "l"(src))
#define CPCOMMIT() asm volatile("cp.async.commit_group;" ::: "memory")
#define CPWAIT2()  asm volatile("cp.async.wait_group 2;" ::: "memory")

#define LDSM4(r0,r1,r2,r3,addr) \
    asm volatile("ldmatrix.sync.aligned.m8n8.x4.shared.b16 {%0,%1,%2,%3}, [%4];" \
                 : "=r"(r0),"=r"(r1),"=r"(r2),"=r"(r3) : "r"(addr))

#define MMA(c,a,b0,b1) \
    asm volatile("mma.sync.aligned.m16n8k16.row.col.f32.bf16.bf16.f32 " \
                 "{%0,%1,%2,%3}, {%4,%5,%6,%7}, {%8,%9}, {%0,%1,%2,%3};" \
                 : "+f"((c)[0]),"+f"((c)[1]),"+f"((c)[2]),"+f"((c)[3]) \
                 : "r"((a)[0]),"r"((a)[1]),"r"((a)[2]),"r"((a)[3]),"r"(b0),"r"(b1))

#define STAGE_BYTES 32768u   // A tile 16KB + B tile 16KB
#define SMEM_BYTES  (3 * 32768)

// ---------------------------------------------------------------------------
// GEMM mainloop: D[128,128] += A[128,K] * B[128,K]^T on packed hi/lo bf16.
// 8 warps (2 in M x 4 in N), warp 64x32, 3 stages cp.async, 3-pass split MMA.
// ---------------------------------------------------------------------------
__device__ __forceinline__ void gemm_main(const uint8_t* __restrict__ Ap,
                                          const uint8_t* __restrict__ Bp,
                                          int KC, char* smem, float (&c)[4][4][4])
{
    const int tid  = threadIdx.x;
    const int lane = tid & 31, wid = tid >> 5;
    const int wm = wid & 1, wn = wid >> 1;
    const uint32_t sb = smem_u32(smem);

    #pragma unroll
    for (int mi = 0; mi < 4; mi++)
        #pragma unroll
        for (int ni = 0; ni < 4; ni++)
            #pragma unroll
            for (int q = 0; q < 4; q++) c[mi][ni][q] = 0.f;

    // loader: thread -> (row, 4 consecutive 16B segs)
    const int lrow = tid >> 1;
    const int ls0  = (tid & 1) * 4;
    const uint8_t* asrc = Ap + (size_t)lrow * KC * 128 + ls0 * 16;
    const uint8_t* bsrc = Bp + (size_t)lrow * KC * 128 + ls0 * 16;
    uint32_t dsw[4];
    #pragma unroll
    for (int i = 0; i < 4; i++)
        dsw[i] = (uint32_t)(lrow * 128 + (((ls0 + i) * 16) ^ ((lrow & 7) << 4)));

    auto issue = [&](int kt, int st) {
        const uint32_t base = sb + (uint32_t)st * STAGE_BYTES;
        const uint8_t* a = asrc + (size_t)kt * 128;
        const uint8_t* b = bsrc + (size_t)kt * 128;
        #pragma unroll
        for (int i = 0; i < 4; i++) CP16(base + dsw[i], a + i * 16);
        #pragma unroll
        for (int i = 0; i < 4; i++) CP16(base + 16384u + dsw[i], b + i * 16);
    };

    issue(0, 0); CPCOMMIT();
    issue(1, 1); CPCOMMIT();
    issue(2, 2); CPCOMMIT();

    const int l15  = lane & 15;
    const int lseg = (lane >> 4) * 16;

    for (int kt = 0; kt < KC; kt++) {
        const int st = kt % 3;
        CPWAIT2();
        __syncthreads();
        const uint32_t Ab = sb + (uint32_t)st * STAGE_BYTES;
        const uint32_t Bb = Ab + 16384u;

        #pragma unroll
        for (int ks = 0; ks < 2; ks++) {
            const int cbh = ks * 32 + lseg;          // hi bytes [0,64)
            uint32_t a[4][4], bh[4][2], bl[4][2];
            #pragma unroll
            for (int mi = 0; mi < 4; mi++) {
                int row = wm * 64 + mi * 16 + l15;
                uint32_t ad = Ab + row * 128 + (cbh ^ ((row & 7) << 4));
                LDSM4(a[mi][0], a[mi][1], a[mi][2], a[mi][3], ad);
            }
            #pragma unroll
            for (int g = 0; g < 2; g++) {
                int row = wn * 32 + g * 16 + l15;
                uint32_t xr = (row & 7) << 4;
                uint32_t r0, r1, r2, r3;
                LDSM4(r0, r1, r2, r3, Bb + row * 128 + (cbh ^ xr));
                bh[2*g][0] = r0; bh[2*g][1] = r2;
                bh[2*g+1][0] = r1; bh[2*g+1][1] = r3;
                LDSM4(r0, r1, r2, r3, Bb + row * 128 + ((cbh + 64) ^ xr));
                bl[2*g][0] = r0; bl[2*g][1] = r2;
                bl[2*g+1][0] = r1; bl[2*g+1][1] = r3;
            }
            #pragma unroll
            for (int mi = 0; mi < 4; mi++)
                #pragma unroll
                for (int ni = 0; ni < 4; ni++)
                    MMA(c[mi][ni], a[mi], bh[ni][0], bh[ni][1]);   // hi*hi
            #pragma unroll
            for (int mi = 0; mi < 4; mi++)
                #pragma unroll
                for (int ni = 0; ni < 4; ni++)
                    MMA(c[mi][ni], a[mi], bl[ni][0], bl[ni][1]);   // hi*lo
            #pragma unroll
            for (int mi = 0; mi < 4; mi++) {                       // reload A lo
                int row = wm * 64 + mi * 16 + l15;
                uint32_t ad = Ab + row * 128 + ((cbh + 64) ^ ((row & 7) << 4));
                LDSM4(a[mi][0], a[mi][1], a[mi][2], a[mi][3], ad);
            }
            #pragma unroll
            for (int mi = 0; mi < 4; mi++)
                #pragma unroll
                for (int ni = 0; ni < 4; ni++)
                    MMA(c[mi][ni], a[mi], bh[ni][0], bh[ni][1]);   // lo*hi
        }
        __syncthreads();
        if (kt + 3 < KC) issue(kt + 3, st);
        CPCOMMIT();
    }
}

// ---------------------------------------------------------------------------
// Prep kernels
// ---------------------------------------------------------------------------
// which: 0 -> g_x1p, 1 -> g_x2p, 2 -> g_wp
__global__ __launch_bounds__(256) void pack_kernel(const float* __restrict__ src,
                                                   int K, int which)
{
    uint32_t* dst = which == 0 ? (uint32_t*)g_x1p
                  : which == 1 ? (uint32_t*)g_x2p : (uint32_t*)g_wp;
    const int KC = K >> 5;
    size_t id = (size_t)blockIdx.x * 256 + threadIdx.x;
    size_t k4 = id * 4;
    int row = (int)(k4 / K);
    int k   = (int)(k4 - (size_t)row * K);
    float4 v = *(const float4*)(src + k4);
    uint32_t h0, h1, l0, l1;
    split4(v, h0, h1, l0, l1);
    uint32_t* d = dst + ((size_t)row * KC + (k >> 5)) * 32 + ((k & 31) >> 1);
    *(uint2*)d        = make_uint2(h0, h1);
    *(uint2*)(d + 16) = make_uint2(l0, l1);
}

// x2 [b][j][h] -> g_vtp packed rows=h, k=j
__global__ __launch_bounds__(256) void transpose_pack(const float* __restrict__ X2)
{
    __shared__ float t[32][33];
    const int b  = blockIdx.z;
    const int j0 = blockIdx.x * 32;
    const int h0 = blockIdx.y * 32;
    const int tid = threadIdx.x;
    const int tx = tid & 31, ty = tid >> 5;
    #pragma unroll
    for (int i = 0; i < 4; i++)
        t[ty + i * 8][tx] = X2[((size_t)b * LL + j0 + ty + i * 8) * HH + h0 + tx];
    __syncthreads();
    const int oy = tid >> 3;          // h local 0..31
    const int ox = (tid & 7) * 4;     // j local
    float4 v = make_float4(t[ox][oy], t[ox+1][oy], t[ox+2][oy], t[ox+3][oy]);
    uint32_t h0b, h1b, l0b, l1b;
    split4(v, h0b, h1b, l0b, l1b);
    const size_t row = (size_t)b * HH + h0 + oy;
    uint32_t* d = (uint32_t*)g_vtp + (row * KCA + blockIdx.x) * 32 + (ox >> 1);
    *(uint2*)d        = make_uint2(h0b, h1b);
    *(uint2*)(d + 16) = make_uint2(l0b, l1b);
}

// ---------------------------------------------------------------------------
// GEMM kernels
// ---------------------------------------------------------------------------
__global__ __launch_bounds__(256, 2) void proj_gemm(const float* __restrict__ bias)
{
    extern __shared__ char smem[];
    const int z  = blockIdx.z;
    const int m0 = blockIdx.y * 128;       // global row (across batches)
    const int n0 = blockIdx.x * 128;       // output feature
    const uint8_t* Ap = (const uint8_t*)(z ? g_x2p : g_x1p) + (size_t)m0 * KCP * 128;
    const uint8_t* Bp = (const uint8_t*)g_wp + (size_t)n0 * KCP * 128;

    float c[4][4][4];
    gemm_main(Ap, Bp, KCP, smem, c);

    uint32_t* dst = z ? (uint32_t*)g_ypp : (uint32_t*)g_xpp;
    const int lane = threadIdx.x & 31, wid = threadIdx.x >> 5;
    const int wm = wid & 1, wn = wid >> 1;
    #pragma unroll
    for (int mi = 0; mi < 4; mi++) {
        const int r0 = m0 + wm * 64 + mi * 16 + (lane >> 2);
        #pragma unroll
        for (int ni = 0; ni < 4; ni++) {
            const int gc = n0 + wn * 32 + ni * 8 + 2 * (lane & 3);
            const float b0 = bias[gc], b1 = bias[gc + 1];
            #pragma unroll
            for (int hrow = 0; hrow < 2; hrow++) {
                const int gr = r0 + 8 * hrow;
                float v0 = fmaxf(c[mi][ni][2*hrow + 0] + b0, 0.f);
                float v1 = fmaxf(c[mi][ni][2*hrow + 1] + b1, 0.f);
                __nv_bfloat162 h = __floats2bfloat162_rn(v0, v1);
                float2 f = __bfloat1622float2(h);
                __nv_bfloat162 l = __floats2bfloat162_rn(v0 - f.x, v1 - f.y);
                uint32_t* d = dst + ((size_t)gr * KCP + (gc >> 5)) * 32 + ((gc & 31) >> 1);
                d[0]  = *reinterpret_cast<uint32_t*>(&h);
                d[16] = *reinterpret_cast<uint32_t*>(&l);
            }
        }
    }
}

__global__ __launch_bounds__(256, 2) void scores_gemm()
{
    extern __shared__ char smem[];
    const int b  = blockIdx.z;
    const int m0 = blockIdx.y * 128;
    const int n0 = blockIdx.x * 128;
    const uint8_t* Ap = (const uint8_t*)g_xpp + (size_t)(b * LL + m0) * KCP * 128;
    const uint8_t* Bp = (const uint8_t*)g_ypp + (size_t)(b * LL + n0) * KCP * 128;

    float c[4][4][4];
    gemm_main(Ap, Bp, KCP, smem, c);

    const int lane = threadIdx.x & 31, wid = threadIdx.x >> 5;
    const int wm = wid & 1, wn = wid >> 1;
    float* C = g_sc + ((size_t)b * LL + m0) * LL + n0;
    #pragma unroll
    for (int mi = 0; mi < 4; mi++) {
        const int r0 = wm * 64 + mi * 16 + (lane >> 2);
        #pragma unroll
        for (int ni = 0; ni < 4; ni++) {
            const int cc = wn * 32 + ni * 8 + 2 * (lane & 3);
            *(float2*)(C + (size_t)r0 * LL + cc)       = make_float2(c[mi][ni][0], c[mi][ni][1]);
            *(float2*)(C + (size_t)(r0 + 8) * LL + cc) = make_float2(c[mi][ni][2], c[mi][ni][3]);
        }
    }
}

// masked softmax over L2, fp32 in g_sc -> packed bf16 hi/lo alpha in g_ap
__global__ __launch_bounds__(256) void softmax_pack(const int* __restrict__ mask2)
{
    const int b = blockIdx.y, i = blockIdx.x, tid = threadIdx.x;
    const float* row = g_sc + ((size_t)b * LL + i) * LL;
    const int* mrow = mask2 + (size_t)b * LL;

    float4 s = *(const float4*)(row + tid * 4);
    int4   m = *(const int4*)(mrow + tid * 4);
    float v[4];
    v[0] = m.x ? -INFINITY : s.x;
    v[1] = m.y ? -INFINITY : s.y;
    v[2] = m.z ? -INFINITY : s.z;
    v[3] = m.w ? -INFINITY : s.w;

    float mx = fmaxf(fmaxf(v[0], v[1]), fmaxf(v[2], v[3]));
    #pragma unroll
    for (int o = 16; o > 0; o >>= 1) mx = fmaxf(mx, __shfl_xor_sync(0xffffffffu, mx, o));

    __shared__ float red[8];
    if ((tid & 31) == 0) red[tid >> 5] = mx;
    __syncthreads();
    float bm = red[0];
    #pragma unroll
    for (int w = 1; w < 8; w++) bm = fmaxf(bm, red[w]);

    float e[4];
    float sum = 0.f;
    #pragma unroll
    for (int q = 0; q < 4; q++) { e[q] = expf(v[q] - bm); sum += e[q]; }
    #pragma unroll
    for (int o = 16; o > 0; o >>= 1) sum += __shfl_xor_sync(0xffffffffu, sum, o);

    __syncthreads();
    if ((tid & 31) == 0) red[tid >> 5] = sum;
    __syncthreads();
    float bs = 0.f;
    #pragma unroll
    for (int w = 0; w < 8; w++) bs += red[w];
    const float inv = 1.0f / bs;

    float4 a4 = make_float4(e[0]*inv, e[1]*inv, e[2]*inv, e[3]*inv);
    uint32_t h0, h1, l0, l1;
    split4(a4, h0, h1, l0, l1);
    const int j0 = tid * 4;
    uint32_t* d = (uint32_t*)g_ap + (((size_t)b * LL + i) * KCA + (j0 >> 5)) * 32 + ((j0 & 31) >> 1);
    *(uint2*)d        = make_uint2(h0, h1);
    *(uint2*)(d + 16) = make_uint2(l0, l1);
}

__global__ __launch_bounds__(256, 2) void att_gemm(const float* __restrict__ X1,
                                                   float* __restrict__ OUT)
{
    extern __shared__ char smem[];
    const int b  = blockIdx.z;
    const int m0 = blockIdx.y * 128;
    const int n0 = blockIdx.x * 128;   // h tile
    const uint8_t* Ap = (const uint8_t*)g_ap  + (size_t)(b * LL + m0) * KCA * 128;
    const uint8_t* Bp = (const uint8_t*)g_vtp + (size_t)(b * HH + n0) * KCA * 128;

    float c[4][4][4];
    gemm_main(Ap, Bp, KCA, smem, c);

    const int lane = threadIdx.x & 31, wid = threadIdx.x >> 5;
    const int wm = wid & 1, wn = wid >> 1;
    #pragma unroll
    for (int mi = 0; mi < 4; mi++) {
        const int r0 = m0 + wm * 64 + mi * 16 + (lane >> 2);
        #pragma unroll
        for (int ni = 0; ni < 4; ni++) {
            const int cc = wn * 32 + ni * 8 + 2 * (lane & 3);
            #pragma unroll
            for (int hrow = 0; hrow < 2; hrow++) {
                const int gr = r0 + 8 * hrow;
                float2 a = make_float2(c[mi][ni][2*hrow + 0], c[mi][ni][2*hrow + 1]);
                const float* xp = X1  + ((size_t)b * LL + gr) * HH   + n0 + cc;
                float*       op = OUT + ((size_t)b * LL + gr) * OUTW + n0 + cc;
                float2 x = *(const float2*)xp;
                *(float2*)(op)          = x;                                  // x1
                *(float2*)(op + HH)     = a;                                  // att
                *(float2*)(op + 2*HH)   = make_float2(x.x * a.x, x.y * a.y);  // x1*att
                *(float2*)(op + 3*HH)   = make_float2(x.x - a.x, x.y - a.y);  // x1-att
            }
        }
    }
}

// ---------------------------------------------------------------------------
// Launch: inputs in metadata order x1, x2, x1_mask(unused), x2_mask, W, b
// ---------------------------------------------------------------------------
extern "C" void kernel_launch(void* const* d_in, const int* in_sizes, int n_in,
                              void* d_out, int out_size)
{
    (void)in_sizes; (void)n_in; (void)out_size;
    const float* x1   = (const float*)d_in[0];
    const float* x2   = (const float*)d_in[1];
    const int*   x2m  = (const int*)d_in[3];
    const float* W    = (const float*)d_in[4];
    const float* bias = (const float*)d_in[5];
    float*       out  = (float*)d_out;

    cudaFuncSetAttribute(proj_gemm,   cudaFuncAttributeMaxDynamicSharedMemorySize, SMEM_BYTES);
    cudaFuncSetAttribute(scores_gemm, cudaFuncAttributeMaxDynamicSharedMemorySize, SMEM_BYTES);
    cudaFuncSetAttribute(att_gemm,    cudaFuncAttributeMaxDynamicSharedMemorySize, SMEM_BYTES);

    pack_kernel<<<(NB*LL*HH/4)/256, 256>>>(x1, HH, 0);   // 12288 blocks
    pack_kernel<<<(NB*LL*HH/4)/256, 256>>>(x2, HH, 1);
    pack_kernel<<<(HH*HH/4)/256,    256>>>(W,  HH, 2);   // 576 blocks

    dim3 gT(LL/32, HH/32, NB);                           // (32, 24, 16)
    transpose_pack<<<gT, 256>>>(x2);

    dim3 gP(HH/128, (NB*LL)/128, 2);                     // (6, 128, 2)
    proj_gemm<<<gP, 256, SMEM_BYTES>>>(bias);

    dim3 gS(LL/128, LL/128, NB);                         // (8, 8, 16)
    scores_gemm<<<gS, 256, SMEM_BYTES>>>();

    dim3 gM(LL, NB);                                     // (1024, 16)
    softmax_pack<<<gM, 256>>>(x2m);

    dim3 gA(HH/128, LL/128, NB);                         // (6, 8, 16)
    att_gemm<<<gA, 256, SMEM_BYTES>>>(x1, out);
}